// round 12
// baseline (speedup 1.0000x reference)
#include <cuda_runtime.h>

// Problem constants: B=8, N=128, IN_DIM=128, C=64 (edge dim), H=8, K=64, HK=512.

__device__ float g_Qh[1024 * 512];
__device__ float g_Kh[1024 * 512];   // pre-scaled by K^-0.5
__device__ float g_Vh[1024 * 512];
__device__ float g_Q2[1024 * 512];
__device__ float g_K2[1024 * 512];   // pre-scaled by K^-0.5
__device__ float g_sc[64 * 128 * 128]; // scores [b*8+h][i][j]
__device__ float g_WTh[5 * 512 * 128]; // transposed {Wq,Wk,Wv,Wq2,Wk2}[col][c]
__device__ float g_WTe[2 * 512 * 64];  // transposed {We,We2}[col][c]

// ---------------------------------------------------------------------------
// Helpers
// ---------------------------------------------------------------------------
__device__ __forceinline__ float f2tf(float x) {
    unsigned u;
    asm("cvt.rna.tf32.f32 %0, %1;" : "=r"(u) : "f"(x));
    return __uint_as_float(u);
}

__device__ __forceinline__ void mma8(float acc[4],
                                     unsigned a0, unsigned a1,
                                     unsigned a2, unsigned a3,
                                     unsigned b0, unsigned b1)
{
    asm volatile(
        "mma.sync.aligned.m16n8k8.row.col.f32.tf32.tf32.f32 "
        "{%0,%1,%2,%3}, {%4,%5,%6,%7}, {%8,%9}, {%0,%1,%2,%3};"
        : "+f"(acc[0]), "+f"(acc[1]), "+f"(acc[2]), "+f"(acc[3])
        : "r"(a0), "r"(a1), "r"(a2), "r"(a3), "r"(b0), "r"(b1));
}

// Within-chunk word for column c: pairs (c, c+4) adjacent for LDS.64 frags.
__device__ __forceinline__ int withinc(int c) {
    return ((c & 3) << 1) | ((c >> 2) & 1);
}

// ---------------------------------------------------------------------------
// Kernel 0: weight transpose (+scale fold for Wk/Wk2).
// ---------------------------------------------------------------------------
__global__ __launch_bounds__(256) void transpose_kernel(
    const float* __restrict__ Wq, const float* __restrict__ Wk,
    const float* __restrict__ Wv, const float* __restrict__ Wq2,
    const float* __restrict__ Wk2, const float* __restrict__ We,
    const float* __restrict__ We2)
{
    __shared__ float t[32][33];
    int m = blockIdx.z;
    int n0 = blockIdx.x * 32, c0 = blockIdx.y * 32;
    int IN = (m < 5) ? 128 : 64;
    if (c0 >= IN) return;
    const float* src;
    float* dst;
    float scale = 1.0f;
    switch (m) {
        case 0: src = Wq;  dst = g_WTh;                break;
        case 1: src = Wk;  dst = g_WTh + 512 * 128;    scale = 0.125f; break;
        case 2: src = Wv;  dst = g_WTh + 2 * 512 * 128; break;
        case 3: src = Wq2; dst = g_WTh + 3 * 512 * 128; break;
        case 4: src = Wk2; dst = g_WTh + 4 * 512 * 128; scale = 0.125f; break;
        case 5: src = We;  dst = g_WTe;                break;
        default: src = We2; dst = g_WTe + 512 * 64;    break;
    }
    int tx = threadIdx.x & 31, ty = threadIdx.x >> 5;
#pragma unroll
    for (int i = 0; i < 4; ++i)
        t[ty + i * 8][tx] = src[(c0 + ty + i * 8) * 512 + n0 + tx] * scale;
    __syncthreads();
#pragma unroll
    for (int i = 0; i < 4; ++i)
        dst[(long)(n0 + ty + i * 8) * IN + c0 + tx] = t[tx][ty + i * 8];
}

// ---------------------------------------------------------------------------
// Kernel 1: projections via SPLIT tf32 MMA (3-term: hi*hi + lo*hi + hi*lo
// with lo = tf32(x - tf32(x))) -> ~fp32 accuracy on Q/K/V.
// ---------------------------------------------------------------------------
__global__ __launch_bounds__(256) void proj_kernel(const float* __restrict__ h)
{
    extern __shared__ float sm[];
    float* Ah = sm;            // [64 rows][64 words] xor-swizzled
    float* Al = Ah + 4096;
    float* Bh = Al + 4096;
    float* Bl = Bh + 4096;     // 64 KB total
    int tid = threadIdx.x;
    int lane = tid & 31, warp = tid >> 5;
    int q = lane & 3, r = lane >> 2;
    int col0 = blockIdx.x * 64, row0 = blockIdx.y * 64;
    int z = blockIdx.z;
    float* dst;
    switch (z) {
        case 0: dst = g_Qh; break;
        case 1: dst = g_Kh; break;
        case 2: dst = g_Vh; break;
        case 3: dst = g_Q2; break;
        default: dst = g_K2; break;
    }
    const float* WT = g_WTh + (long)z * 512 * 128;

    int mt = warp >> 1;
    int nts = (warp & 1) * 4;
    float acc[4][4];
#pragma unroll
    for (int t = 0; t < 4; ++t)
#pragma unroll
        for (int m = 0; m < 4; ++m) acc[t][m] = 0.0f;

    for (int ck = 0; ck < 2; ++ck) {
        __syncthreads();
        for (int f = tid; f < 4096; f += 256) {
            int rr = f >> 6, c = f & 63;
            int off = rr * 64 + ((((c >> 3) ^ (rr & 7)) << 3) | withinc(c));
            float av = h[(row0 + rr) * 128 + ck * 64 + c];
            float ah = f2tf(av);
            Ah[off] = ah; Al[off] = f2tf(av - ah);
            float bv = WT[(long)(col0 + rr) * 128 + ck * 64 + c];
            float bh = f2tf(bv);
            Bh[off] = bh; Bl[off] = f2tf(bv - bh);
        }
        __syncthreads();

        for (int kc = 0; kc < 8; ++kc) {
            int pc = ((kc ^ r) << 3) + q * 2;
            int a0off = (mt * 16 + r) * 64 + pc;
            int a1off = (mt * 16 + 8 + r) * 64 + pc;
            uint2 Ah0 = *(const uint2*)&Ah[a0off];
            uint2 Ah1 = *(const uint2*)&Ah[a1off];
            uint2 Al0 = *(const uint2*)&Al[a0off];
            uint2 Al1 = *(const uint2*)&Al[a1off];
#pragma unroll
            for (int t = 0; t < 4; ++t) {
                int boff = ((nts + t) * 8 + r) * 64 + pc;
                uint2 Bhv = *(const uint2*)&Bh[boff];
                uint2 Blv = *(const uint2*)&Bl[boff];
                mma8(acc[t], Ah0.x, Ah1.x, Ah0.y, Ah1.y, Bhv.x, Bhv.y);
                mma8(acc[t], Al0.x, Al1.x, Al0.y, Al1.y, Bhv.x, Bhv.y);
                mma8(acc[t], Ah0.x, Ah1.x, Ah0.y, Ah1.y, Blv.x, Blv.y);
            }
        }
    }

#pragma unroll
    for (int t = 0; t < 4; ++t) {
        long b0 = (long)(row0 + mt * 16 + r) * 512 + col0 + (nts + t) * 8 + q * 2;
        long b1 = b0 + 8L * 512;
        *(float2*)&dst[b0] = make_float2(acc[t][0], acc[t][1]);
        *(float2*)&dst[b1] = make_float2(acc[t][2], acc[t][3]);
    }
}

// ---------------------------------------------------------------------------
// Kernel 2: tensor-core scores. Grid = (b, i, head-group of 4).
// 256 threads = 8 warps = (head_in_group, k-half); each warp loops 2
// k-quarters with Bv[2][8] register B-fragments (32 regs) -> 3 blocks/SM.
// Partials stored to sc_s[part][head][j] (no atomics; padded slots store
// duplicate identical values). Final write sums 4 partials.
// ---------------------------------------------------------------------------
__global__ __launch_bounds__(256, 3) void score_kernel(
    const float* __restrict__ e, const unsigned* __restrict__ adjw)
{
    extern __shared__ float sm[];
    float* e_s  = sm;                 // [144 slots][64 words] xor-swizzled
    float* q1   = e_s + 144 * 64;     // [512]
    float* q2   = q1 + 512;           // [512]
    float* sc_s = q2 + 512;           // [4 part][4 head][128 j]
    int*   cnt  = (int*)(sc_s + 2048);
    unsigned char* jlA    = (unsigned char*)(cnt + 2);   // [128]
    unsigned char* jlB    = jlA + 128;                   // [128]
    unsigned char* slot_j = jlB + 128;                   // [144]

    int tid = threadIdx.x;
    int lane = tid & 31, warp = tid >> 5;
    int q = lane & 3, r = lane >> 2;
    int head_local = warp >> 1, half = warp & 1;
    int blk = blockIdx.x;
    int hg = blk & 1, i = (blk >> 1) & 127, b = blk >> 8;
    int head = hg * 4 + head_local;
    long base_e = ((long)(b * 128 + i)) * 8192;

    if (tid < 2) cnt[tid] = 0;
    __syncthreads();
    if (tid < 128) {
        unsigned a = adjw[(b * 128 + i) * 128 + tid];
        int lst = (a != 0u) ? 0 : 1;
        int pos = atomicAdd(&cnt[lst], 1);
        (lst == 0 ? jlA : jlB)[pos] = (unsigned char)tid;
    }
    q1[tid]       = g_Qh[(long)(b * 128 + i) * 512 + tid];
    q1[tid + 256] = g_Qh[(long)(b * 128 + i) * 512 + tid + 256];
    q2[tid]       = g_Q2[(long)(b * 128 + i) * 512 + tid];
    q2[tid + 256] = g_Q2[(long)(b * 128 + i) * 512 + tid + 256];
    __syncthreads();

    int n1 = cnt[0], n2 = cnt[1];
    int n1p = n1 ? ((n1 + 15) & ~15) : 0;
    int n2p = n2 ? ((n2 + 15) & ~15) : 0;
    int T1 = n1p >> 4;
    int T = (n1p + n2p) >> 4;
    int nslot = T << 4;
    if (tid < n1p) {
        slot_j[tid] = jlA[tid < n1 ? tid : n1 - 1];
    } else if (tid - n1p < n2p) {
        int s2 = tid - n1p;
        slot_j[tid] = jlB[s2 < n2 ? s2 : n2 - 1];
    }
    __syncthreads();

    // Load e rows in sorted slot order (xor-swizzled, tf32)
    for (int f = tid; f < nslot * 64; f += 256) {
        int slot = f >> 6, c = f & 63;
        int j = slot_j[slot];
        int off = slot * 64 + ((((c >> 3) ^ (slot & 7)) << 3) | withinc(c));
        e_s[off] = f2tf(e[base_e + j * 64 + c]);
    }
    __syncthreads();

    for (int g = 0; g < 2; ++g) {
        int t0 = g ? T1 : 0;
        int t1 = g ? T : T1;
        if (t0 == t1) continue;
        const float* WT = g_WTe + (long)g * 512 * 64;
        const float* qs = g ? q2 : q1;
        const float* Ks = g ? g_K2 : g_Kh;

#pragma unroll
        for (int kq = 0; kq < 2; ++kq) {
            int kbase = head * 64 + half * 32 + kq * 16;
            int part = half * 2 + kq;

            // Build B fragments in registers (k-quarter):
            // Wt[k][c] = We^T[k][c] * Q[i][k]
            uint2 Bv[2][8];
#pragma unroll
            for (int s = 0; s < 2; ++s) {
                int krow = kbase + s * 8 + r;
                float qv = qs[krow];
                const float* wrow = WT + krow * 64;
#pragma unroll
                for (int kc = 0; kc < 8; ++kc) {
                    Bv[s][kc].x = __float_as_uint(f2tf(wrow[kc * 8 + q] * qv));
                    Bv[s][kc].y = __float_as_uint(f2tf(wrow[kc * 8 + q + 4] * qv));
                }
            }

            for (int t = t0; t < t1; ++t) {
                int slot0 = t * 16 + r, slot1 = slot0 + 8;
                float acc[2][4];
#pragma unroll
                for (int s = 0; s < 2; ++s)
#pragma unroll
                    for (int m = 0; m < 4; ++m) acc[s][m] = 0.0f;

#pragma unroll
                for (int kc = 0; kc < 8; ++kc) {
                    int pc = ((kc ^ r) << 3) + q * 2;
                    uint2 A0 = *(const uint2*)&e_s[slot0 * 64 + pc];
                    uint2 A1 = *(const uint2*)&e_s[slot1 * 64 + pc];
                    mma8(acc[0], A0.x, A1.x, A0.y, A1.y,
                         Bv[0][kc].x, Bv[0][kc].y);
                    mma8(acc[1], A0.x, A1.x, A0.y, A1.y,
                         Bv[1][kc].x, Bv[1][kc].y);
                }

                // Epilogue: dot k-quarter with K, quad-reduce, store partial
                int j0 = slot_j[slot0], j1 = slot_j[slot1];
                const float* K0 = Ks + (long)(b * 128 + j0) * 512 + kbase + q * 2;
                const float* K1 = Ks + (long)(b * 128 + j1) * 512 + kbase + q * 2;
                float p0 = 0.0f, p1 = 0.0f;
#pragma unroll
                for (int s = 0; s < 2; ++s) {
                    float2 k0 = *(const float2*)(K0 + s * 8);
                    float2 k1 = *(const float2*)(K1 + s * 8);
                    p0 += acc[s][0] * k0.x + acc[s][1] * k0.y;
                    p1 += acc[s][2] * k1.x + acc[s][3] * k1.y;
                }
                p0 += __shfl_xor_sync(0xffffffffu, p0, 1);
                p0 += __shfl_xor_sync(0xffffffffu, p0, 2);
                p1 += __shfl_xor_sync(0xffffffffu, p1, 1);
                p1 += __shfl_xor_sync(0xffffffffu, p1, 2);
                if (q == 0) {
                    float* dstp = &sc_s[(part * 4 + head_local) * 128];
                    dstp[j0] = p0;   // duplicate-padded slots store identical
                    dstp[j1] = p1;   // values -> plain stores are safe
                }
            }
        }
    }
    __syncthreads();

    for (int idx = tid; idx < 512; idx += 256) {
        int hl = idx >> 7, j = idx & 127;
        float v = sc_s[(0 * 4 + hl) * 128 + j] + sc_s[(1 * 4 + hl) * 128 + j]
                + sc_s[(2 * 4 + hl) * 128 + j] + sc_s[(3 * 4 + hl) * 128 + j];
        g_sc[((long)((b * 8 + hg * 4 + hl) * 128 + i)) * 128 + j] = v;
    }
}

// ---------------------------------------------------------------------------
// Kernel 3: epilogue, no max subtraction (uniform shift cancels in the
// normalization). Block = (b, h, i-tile of 16).
// ---------------------------------------------------------------------------
__global__ __launch_bounds__(256) void out_kernel(
    const float* __restrict__ krw, const float* __restrict__ mask,
    float* __restrict__ out)
{
    __shared__ float Vs[8192];       // [128 j][64 k]
    __shared__ float ms[128];
    int tid = threadIdx.x;
    int lane = tid & 31, warp = tid >> 5;
    int blk = blockIdx.x;
    int b = blk >> 6, h = (blk >> 3) & 7, it = blk & 7;

    for (int f = tid; f < 8192; f += 256) {
        int j = f >> 6, k = f & 63;
        Vs[f] = g_Vh[(long)(b * 128 + j) * 512 + h * 64 + k];
    }
    if (tid < 128) ms[tid] = mask[b * 128 + tid];
    __syncthreads();

#pragma unroll
    for (int rr = 0; rr < 2; ++rr) {
        int i = it * 16 + warp * 2 + rr;
        float mi = ms[i];
        float pm[4];
        float den = 0.0f;
#pragma unroll
        for (int m = 0; m < 4; ++m) {
            int j = m * 32 + lane;
            float s = g_sc[((long)((b * 8 + h) * 128 + i)) * 128 + j];
            float p = __expf(s) * ms[j] * krw[(long)b * 16384 + i * 128 + j];
            pm[m] = p;
            den += p;
        }
#pragma unroll
        for (int o = 16; o; o >>= 1) den += __shfl_xor_sync(0xffffffffu, den, o);
        den = fmaxf(den * mi, 1e-6f);

        float a0 = 0.0f, a1 = 0.0f;
#pragma unroll
        for (int m = 0; m < 4; ++m) {
#pragma unroll 8
            for (int jj = 0; jj < 32; ++jj) {
                float p = __shfl_sync(0xffffffffu, pm[m], jj);
                int j = m * 32 + jj;
                a0 += p * Vs[j * 64 + lane];
                a1 += p * Vs[j * 64 + lane + 32];
            }
        }
        float inv = mi / den;
        long ob = (long)(b * 128 + i) * 512 + h * 64;
        out[ob + lane] = a0 * inv;
        out[ob + lane + 32] = a1 * inv;
    }
}

// ---------------------------------------------------------------------------
extern "C" void kernel_launch(void* const* d_in, const int* in_sizes, int n_in,
                              void* d_out, int out_size)
{
    (void)in_sizes; (void)n_in; (void)out_size;
    const float*    h    = (const float*)d_in[0];
    const float*    e    = (const float*)d_in[1];
    const float*    krw  = (const float*)d_in[2];
    const float*    mask = (const float*)d_in[3];
    const unsigned* adjw = (const unsigned*)d_in[4];
    const float*    Wq   = (const float*)d_in[5];
    const float*    Wk   = (const float*)d_in[6];
    const float*    Wv   = (const float*)d_in[7];
    const float*    We   = (const float*)d_in[8];
    const float*    Wq2  = (const float*)d_in[9];
    const float*    Wk2  = (const float*)d_in[10];
    const float*    We2  = (const float*)d_in[11];
    float* out = (float*)d_out;

    cudaFuncSetAttribute(proj_kernel,
                         cudaFuncAttributeMaxDynamicSharedMemorySize, 65536);
    // score smem: (9216 + 512 + 512 + 2048)*4 + 8 + 400 = 49560 -> 49664
    cudaFuncSetAttribute(score_kernel,
                         cudaFuncAttributeMaxDynamicSharedMemorySize, 49664);

    transpose_kernel<<<dim3(16, 4, 7), 256>>>(Wq, Wk, Wv, Wq2, Wk2, We, We2);
    proj_kernel<<<dim3(8, 16, 5), 256, 65536>>>(h);
    score_kernel<<<2048, 256, 49664>>>(e, adjw);
    out_kernel<<<512, 256>>>(krw, mask, out);
}

// round 13
// speedup vs baseline: 1.3977x; 1.3977x over previous
#include <cuda_runtime.h>
#include <cuda_fp16.h>

// Problem constants: B=8, N=128, IN_DIM=128, C=64 (edge dim), H=8, K=64, HK=512.

__device__ float g_Qh[1024 * 512];
__device__ float g_Kh[1024 * 512];   // pre-scaled by K^-0.5
__device__ float g_Vh[1024 * 512];
__device__ float g_Q2[1024 * 512];
__device__ float g_K2[1024 * 512];   // pre-scaled by K^-0.5
__device__ float g_sc[64 * 128 * 128]; // scores [b*8+h][i][j]
__device__ float g_WTh[5 * 512 * 128]; // transposed {Wq,Wk,Wv,Wq2,Wk2}[col][c]
__device__ float g_WTe[2 * 512 * 64];  // transposed {We,We2}[col][c]

// ---------------------------------------------------------------------------
// Helpers
// ---------------------------------------------------------------------------
__device__ __forceinline__ float f2tf(float x) {
    unsigned u;
    asm("cvt.rna.tf32.f32 %0, %1;" : "=r"(u) : "f"(x));
    return __uint_as_float(u);
}

__device__ __forceinline__ void mma8(float acc[4],
                                     unsigned a0, unsigned a1,
                                     unsigned a2, unsigned a3,
                                     unsigned b0, unsigned b1)
{
    asm volatile(
        "mma.sync.aligned.m16n8k8.row.col.f32.tf32.tf32.f32 "
        "{%0,%1,%2,%3}, {%4,%5,%6,%7}, {%8,%9}, {%0,%1,%2,%3};"
        : "+f"(acc[0]), "+f"(acc[1]), "+f"(acc[2]), "+f"(acc[3])
        : "r"(a0), "r"(a1), "r"(a2), "r"(a3), "r"(b0), "r"(b1));
}

__device__ __forceinline__ void mma16(float acc[4],
                                      unsigned a0, unsigned a1,
                                      unsigned a2, unsigned a3,
                                      unsigned b0, unsigned b1)
{
    asm volatile(
        "mma.sync.aligned.m16n8k16.row.col.f32.f16.f16.f32 "
        "{%0,%1,%2,%3}, {%4,%5,%6,%7}, {%8,%9}, {%0,%1,%2,%3};"
        : "+f"(acc[0]), "+f"(acc[1]), "+f"(acc[2]), "+f"(acc[3])
        : "r"(a0), "r"(a1), "r"(a2), "r"(a3), "r"(b0), "r"(b1));
}

__device__ __forceinline__ unsigned pack_h2(float lo, float hi) {
    __half2 h = __floats2half2_rn(lo, hi);
    return *reinterpret_cast<unsigned*>(&h);
}

// Within-chunk word for column c: pairs (c, c+4) adjacent for LDS.64 frags.
__device__ __forceinline__ int withinc(int c) {
    return ((c & 3) << 1) | ((c >> 2) & 1);
}
// Same idea for half2-pair index p (0..7 within a k16 chunk): p<4 -> 2p,
// p>=4 -> 2(p-4)+1, so a uint2 at slot 2q returns pairs {q, q+4}.
__device__ __forceinline__ int pslot(int p) {
    return ((p & 3) << 1) | (p >> 2);
}

// ---------------------------------------------------------------------------
// Kernel 0: weight transpose (+scale fold for Wk/Wk2).
// ---------------------------------------------------------------------------
__global__ __launch_bounds__(256) void transpose_kernel(
    const float* __restrict__ Wq, const float* __restrict__ Wk,
    const float* __restrict__ Wv, const float* __restrict__ Wq2,
    const float* __restrict__ Wk2, const float* __restrict__ We,
    const float* __restrict__ We2)
{
    __shared__ float t[32][33];
    int m = blockIdx.z;
    int n0 = blockIdx.x * 32, c0 = blockIdx.y * 32;
    int IN = (m < 5) ? 128 : 64;
    if (c0 >= IN) return;
    const float* src;
    float* dst;
    float scale = 1.0f;
    switch (m) {
        case 0: src = Wq;  dst = g_WTh;                break;
        case 1: src = Wk;  dst = g_WTh + 512 * 128;    scale = 0.125f; break;
        case 2: src = Wv;  dst = g_WTh + 2 * 512 * 128; break;
        case 3: src = Wq2; dst = g_WTh + 3 * 512 * 128; break;
        case 4: src = Wk2; dst = g_WTh + 4 * 512 * 128; scale = 0.125f; break;
        case 5: src = We;  dst = g_WTe;                break;
        default: src = We2; dst = g_WTe + 512 * 64;    break;
    }
    int tx = threadIdx.x & 31, ty = threadIdx.x >> 5;
#pragma unroll
    for (int i = 0; i < 4; ++i)
        t[ty + i * 8][tx] = src[(c0 + ty + i * 8) * 512 + n0 + tx] * scale;
    __syncthreads();
#pragma unroll
    for (int i = 0; i < 4; ++i)
        dst[(long)(n0 + ty + i * 8) * IN + c0 + tx] = t[tx][ty + i * 8];
}

// ---------------------------------------------------------------------------
// Kernel 1: projections via SPLIT tf32 MMA (3-term: hi*hi + lo*hi + hi*lo
// with lo = tf32(x - tf32(x))) -> ~fp32 accuracy on Q/K/V.
// ---------------------------------------------------------------------------
__global__ __launch_bounds__(256) void proj_kernel(const float* __restrict__ h)
{
    extern __shared__ float sm[];
    float* Ah = sm;            // [64 rows][64 words] xor-swizzled
    float* Al = Ah + 4096;
    float* Bh = Al + 4096;
    float* Bl = Bh + 4096;     // 64 KB total
    int tid = threadIdx.x;
    int lane = tid & 31, warp = tid >> 5;
    int q = lane & 3, r = lane >> 2;
    int col0 = blockIdx.x * 64, row0 = blockIdx.y * 64;
    int z = blockIdx.z;
    float* dst;
    switch (z) {
        case 0: dst = g_Qh; break;
        case 1: dst = g_Kh; break;
        case 2: dst = g_Vh; break;
        case 3: dst = g_Q2; break;
        default: dst = g_K2; break;
    }
    const float* WT = g_WTh + (long)z * 512 * 128;

    int mt = warp >> 1;
    int nts = (warp & 1) * 4;
    float acc[4][4];
#pragma unroll
    for (int t = 0; t < 4; ++t)
#pragma unroll
        for (int m = 0; m < 4; ++m) acc[t][m] = 0.0f;

    for (int ck = 0; ck < 2; ++ck) {
        __syncthreads();
        for (int f = tid; f < 4096; f += 256) {
            int rr = f >> 6, c = f & 63;
            int off = rr * 64 + ((((c >> 3) ^ (rr & 7)) << 3) | withinc(c));
            float av = h[(row0 + rr) * 128 + ck * 64 + c];
            float ah = f2tf(av);
            Ah[off] = ah; Al[off] = f2tf(av - ah);
            float bv = WT[(long)(col0 + rr) * 128 + ck * 64 + c];
            float bh = f2tf(bv);
            Bh[off] = bh; Bl[off] = f2tf(bv - bh);
        }
        __syncthreads();

        for (int kc = 0; kc < 8; ++kc) {
            int pc = ((kc ^ r) << 3) + q * 2;
            int a0off = (mt * 16 + r) * 64 + pc;
            int a1off = (mt * 16 + 8 + r) * 64 + pc;
            uint2 Ah0 = *(const uint2*)&Ah[a0off];
            uint2 Ah1 = *(const uint2*)&Ah[a1off];
            uint2 Al0 = *(const uint2*)&Al[a0off];
            uint2 Al1 = *(const uint2*)&Al[a1off];
#pragma unroll
            for (int t = 0; t < 4; ++t) {
                int boff = ((nts + t) * 8 + r) * 64 + pc;
                uint2 Bhv = *(const uint2*)&Bh[boff];
                uint2 Blv = *(const uint2*)&Bl[boff];
                mma8(acc[t], Ah0.x, Ah1.x, Ah0.y, Ah1.y, Bhv.x, Bhv.y);
                mma8(acc[t], Al0.x, Al1.x, Al0.y, Al1.y, Bhv.x, Bhv.y);
                mma8(acc[t], Ah0.x, Ah1.x, Ah0.y, Ah1.y, Blv.x, Blv.y);
            }
        }
    }

#pragma unroll
    for (int t = 0; t < 4; ++t) {
        long b0 = (long)(row0 + mt * 16 + r) * 512 + col0 + (nts + t) * 8 + q * 2;
        long b1 = b0 + 8L * 512;
        *(float2*)&dst[b0] = make_float2(acc[t][0], acc[t][1]);
        *(float2*)&dst[b1] = make_float2(acc[t][2], acc[t][3]);
    }
}

// ---------------------------------------------------------------------------
// Kernel 2: fp16 tensor-core scores (m16n8k16, fp32 accum).
// Block = (b,i), 512 threads = 16 warps = (head, k-half).
// e rows in smem as half2, sorted-slot order, 32-uint rows, 4-chunk XOR
// swizzle (conflict-free LDS.64). B-fragments (Q-folded We^T) built in
// registers per branch from L2 (vectorized float2 loads).
// K-half partials -> separate smem arrays (plain idempotent stores).
// ---------------------------------------------------------------------------
__global__ __launch_bounds__(512) void score_kernel(
    const float* __restrict__ e, const unsigned* __restrict__ adjw)
{
    extern __shared__ float sm[];
    unsigned* e_u = (unsigned*)sm;    // [144 slots][32 half2-units] swizzled
    float* q1   = sm + 4608;          // [512]
    float* q2   = q1 + 512;           // [512]
    float* sc_s = q2 + 512;           // [2 khalf][8 head][128 j]
    int*   cnt  = (int*)(sc_s + 2048);
    unsigned char* jlA    = (unsigned char*)(cnt + 2);   // [128]
    unsigned char* jlB    = jlA + 128;                   // [128]
    unsigned char* slot_j = jlB + 128;                   // [144]

    int tid = threadIdx.x;
    int lane = tid & 31, warp = tid >> 5;
    int q = lane & 3, r = lane >> 2;
    int head = warp >> 1, half = warp & 1;
    int b = blockIdx.x >> 7, i = blockIdx.x & 127;
    long base_e = ((long)(b * 128 + i)) * 8192;

    if (tid < 2) cnt[tid] = 0;
    __syncthreads();
    if (tid < 128) {
        unsigned a = adjw[(b * 128 + i) * 128 + tid];
        int lst = (a != 0u) ? 0 : 1;
        int pos = atomicAdd(&cnt[lst], 1);
        (lst == 0 ? jlA : jlB)[pos] = (unsigned char)tid;
    }
    q1[tid] = g_Qh[(long)(b * 128 + i) * 512 + tid];
    q2[tid] = g_Q2[(long)(b * 128 + i) * 512 + tid];
    __syncthreads();

    int n1 = cnt[0], n2 = cnt[1];
    int n1p = n1 ? ((n1 + 15) & ~15) : 0;
    int n2p = n2 ? ((n2 + 15) & ~15) : 0;
    int T1 = n1p >> 4;
    int T = (n1p + n2p) >> 4;
    int nslot = T << 4;
    if (tid < n1p) {
        slot_j[tid] = jlA[tid < n1 ? tid : n1 - 1];
    } else if (tid - n1p < n2p) {
        int s2 = tid - n1p;
        slot_j[tid] = jlB[s2 < n2 ? s2 : n2 - 1];
    }
    __syncthreads();

    // Load e rows (sorted slot order) as half2, swizzled.
    // float4 covers c = 4t..4t+3 = half2-pairs p=2t (even) and 2t+1.
    for (int f = tid; f < nslot * 16; f += 512) {
        int slot = f >> 4, t4 = f & 15;
        int j = slot_j[slot];
        float4 v = *(const float4*)&e[base_e + j * 64 + t4 * 4];
        int chunk = t4 >> 2;                    // k16-chunk (0..3)
        int phys = (chunk ^ (slot & 3)) << 3;
        int pw0 = (2 * t4) & 7;                 // even pair in chunk
        unsigned* row = e_u + slot * 32 + phys;
        row[pslot(pw0)]     = pack_h2(v.x, v.y);
        row[pslot(pw0 + 1)] = pack_h2(v.z, v.w);
    }
    __syncthreads();

    int kbase = head * 64 + half * 32;
    for (int g = 0; g < 2; ++g) {
        int t0 = g ? T1 : 0;
        int t1 = g ? T : T1;
        if (t0 == t1) continue;
        const float* WT = g_WTe + (long)g * 512 * 64;
        const float* qs = g ? q2 : q1;
        const float* Ks = g ? g_K2 : g_Kh;

        // Build fp16 B fragments in registers:
        // Wt[k][c] = We^T[k][c] * Q[i][k], c in chunks of 16 (MMA-k).
        // b0 = {Wt[n][kc*16+2q], [..+2q+1]}, b1 = {.. +2q+8, +2q+9}, n = s*8+r.
        uint2 Bv[4][4];
#pragma unroll
        for (int s = 0; s < 4; ++s) {
            int krow = kbase + s * 8 + r;
            float qv = qs[krow];
            const float* wrow = WT + krow * 64;
#pragma unroll
            for (int kc = 0; kc < 4; ++kc) {
                float2 w0 = *(const float2*)&wrow[kc * 16 + 2 * q];
                float2 w1 = *(const float2*)&wrow[kc * 16 + 2 * q + 8];
                Bv[s][kc].x = pack_h2(w0.x * qv, w0.y * qv);
                Bv[s][kc].y = pack_h2(w1.x * qv, w1.y * qv);
            }
        }

        for (int t = t0; t < t1; ++t) {
            int slot0 = t * 16 + r, slot1 = slot0 + 8;
            float acc[4][4];
#pragma unroll
            for (int s = 0; s < 4; ++s)
#pragma unroll
                for (int m = 0; m < 4; ++m) acc[s][m] = 0.0f;

#pragma unroll
            for (int kc = 0; kc < 4; ++kc) {
                int pc = ((kc ^ (r & 3)) << 3) + 2 * q;
                uint2 A0 = *(const uint2*)(e_u + slot0 * 32 + pc);
                uint2 A1 = *(const uint2*)(e_u + slot1 * 32 + pc);
#pragma unroll
                for (int s = 0; s < 4; ++s)
                    mma16(acc[s], A0.x, A1.x, A0.y, A1.y,
                          Bv[s][kc].x, Bv[s][kc].y);
            }

            // Epilogue: dot k-half with K, quad-reduce, store partial.
            int j0 = slot_j[slot0], j1 = slot_j[slot1];
            const float* K0 = Ks + (long)(b * 128 + j0) * 512 + kbase + q * 2;
            const float* K1 = Ks + (long)(b * 128 + j1) * 512 + kbase + q * 2;
            float p0 = 0.0f, p1 = 0.0f;
#pragma unroll
            for (int s = 0; s < 4; ++s) {
                float2 k0 = *(const float2*)(K0 + s * 8);
                float2 k1 = *(const float2*)(K1 + s * 8);
                p0 += acc[s][0] * k0.x + acc[s][1] * k0.y;
                p1 += acc[s][2] * k1.x + acc[s][3] * k1.y;
            }
            p0 += __shfl_xor_sync(0xffffffffu, p0, 1);
            p0 += __shfl_xor_sync(0xffffffffu, p0, 2);
            p1 += __shfl_xor_sync(0xffffffffu, p1, 1);
            p1 += __shfl_xor_sync(0xffffffffu, p1, 2);
            if (q == 0) {
                float* dstp = &sc_s[(half * 8 + head) * 128];
                dstp[j0] = p0;   // duplicate-padded slots store identical
                dstp[j1] = p1;   // values -> plain stores are safe
            }
        }
    }
    __syncthreads();

    for (int idx = tid; idx < 1024; idx += 512) {
        int hh = idx >> 7, j = idx & 127;
        float v = sc_s[hh * 128 + j] + sc_s[1024 + hh * 128 + j];
        g_sc[((long)((b * 8 + hh) * 128 + i)) * 128 + j] = v;
    }
}

// ---------------------------------------------------------------------------
// Kernel 3: epilogue, no max subtraction (uniform shift cancels in the
// normalization). Block = (b, h, i-tile of 16).
// ---------------------------------------------------------------------------
__global__ __launch_bounds__(256) void out_kernel(
    const float* __restrict__ krw, const float* __restrict__ mask,
    float* __restrict__ out)
{
    __shared__ float Vs[8192];       // [128 j][64 k]
    __shared__ float ms[128];
    int tid = threadIdx.x;
    int lane = tid & 31, warp = tid >> 5;
    int blk = blockIdx.x;
    int b = blk >> 6, h = (blk >> 3) & 7, it = blk & 7;

    for (int f = tid; f < 8192; f += 256) {
        int j = f >> 6, k = f & 63;
        Vs[f] = g_Vh[(long)(b * 128 + j) * 512 + h * 64 + k];
    }
    if (tid < 128) ms[tid] = mask[b * 128 + tid];
    __syncthreads();

#pragma unroll
    for (int rr = 0; rr < 2; ++rr) {
        int i = it * 16 + warp * 2 + rr;
        float mi = ms[i];
        float pm[4];
        float den = 0.0f;
#pragma unroll
        for (int m = 0; m < 4; ++m) {
            int j = m * 32 + lane;
            float s = g_sc[((long)((b * 8 + h) * 128 + i)) * 128 + j];
            float p = __expf(s) * ms[j] * krw[(long)b * 16384 + i * 128 + j];
            pm[m] = p;
            den += p;
        }
#pragma unroll
        for (int o = 16; o; o >>= 1) den += __shfl_xor_sync(0xffffffffu, den, o);
        den = fmaxf(den * mi, 1e-6f);

        float a0 = 0.0f, a1 = 0.0f;
#pragma unroll
        for (int m = 0; m < 4; ++m) {
#pragma unroll 8
            for (int jj = 0; jj < 32; ++jj) {
                float p = __shfl_sync(0xffffffffu, pm[m], jj);
                int j = m * 32 + jj;
                a0 += p * Vs[j * 64 + lane];
                a1 += p * Vs[j * 64 + lane + 32];
            }
        }
        float inv = mi / den;
        long ob = (long)(b * 128 + i) * 512 + h * 64;
        out[ob + lane] = a0 * inv;
        out[ob + lane + 32] = a1 * inv;
    }
}

// ---------------------------------------------------------------------------
extern "C" void kernel_launch(void* const* d_in, const int* in_sizes, int n_in,
                              void* d_out, int out_size)
{
    (void)in_sizes; (void)n_in; (void)out_size;
    const float*    h    = (const float*)d_in[0];
    const float*    e    = (const float*)d_in[1];
    const float*    krw  = (const float*)d_in[2];
    const float*    mask = (const float*)d_in[3];
    const unsigned* adjw = (const unsigned*)d_in[4];
    const float*    Wq   = (const float*)d_in[5];
    const float*    Wk   = (const float*)d_in[6];
    const float*    Wv   = (const float*)d_in[7];
    const float*    We   = (const float*)d_in[8];
    const float*    Wq2  = (const float*)d_in[9];
    const float*    Wk2  = (const float*)d_in[10];
    const float*    We2  = (const float*)d_in[11];
    float* out = (float*)d_out;

    cudaFuncSetAttribute(proj_kernel,
                         cudaFuncAttributeMaxDynamicSharedMemorySize, 65536);
    // score smem: 4608*4 (e half2) + 1024*4 (q) + 2048*4 (sc) + 8 + 400
    //           = 31128 -> 31232 B
    cudaFuncSetAttribute(score_kernel,
                         cudaFuncAttributeMaxDynamicSharedMemorySize, 31232);

    transpose_kernel<<<dim3(16, 4, 7), 256>>>(Wq, Wk, Wv, Wq2, Wk2, We, We2);
    proj_kernel<<<dim3(8, 16, 5), 256, 65536>>>(h);
    score_kernel<<<1024, 512, 31232>>>(e, adjw);
    out_kernel<<<512, 256>>>(krw, mask, out);
}

// round 14
// speedup vs baseline: 1.6080x; 1.1505x over previous
#include <cuda_runtime.h>
#include <cuda_fp16.h>

// Problem constants: B=8, N=128, IN_DIM=128, C=64 (edge dim), H=8, K=64, HK=512.

__device__ float g_Qh[1024 * 512];
__device__ float g_Kh[1024 * 512];   // pre-scaled by K^-0.5
__device__ float g_Vh[1024 * 512];
__device__ float g_Q2[1024 * 512];
__device__ float g_K2[1024 * 512];   // pre-scaled by K^-0.5
__device__ float g_sc[64 * 128 * 128]; // scores [b*8+h][i][j]
__device__ float g_WTh[5 * 512 * 128]; // transposed {Wq,Wk,Wv,Wq2,Wk2}[col][c]
// Pre-packed half2 We fragments in MMA B-register order:
// entry (g, k, q, kc) -> 2 unsigned: {h2(Wt[k][kc*16+2q], ..+1), h2(..+8, ..+9)}
// with Wt[k][c] = We_g[c][k]. Layout: ((g*512 + k)*4 + q)*8 + kc*2 (+1).
__device__ unsigned g_WTeh[2 * 512 * 4 * 8];

// ---------------------------------------------------------------------------
// Helpers
// ---------------------------------------------------------------------------
__device__ __forceinline__ float f2tf(float x) {
    unsigned u;
    asm("cvt.rna.tf32.f32 %0, %1;" : "=r"(u) : "f"(x));
    return __uint_as_float(u);
}

__device__ __forceinline__ void mma8(float acc[4],
                                     unsigned a0, unsigned a1,
                                     unsigned a2, unsigned a3,
                                     unsigned b0, unsigned b1)
{
    asm volatile(
        "mma.sync.aligned.m16n8k8.row.col.f32.tf32.tf32.f32 "
        "{%0,%1,%2,%3}, {%4,%5,%6,%7}, {%8,%9}, {%0,%1,%2,%3};"
        : "+f"(acc[0]), "+f"(acc[1]), "+f"(acc[2]), "+f"(acc[3])
        : "r"(a0), "r"(a1), "r"(a2), "r"(a3), "r"(b0), "r"(b1));
}

__device__ __forceinline__ void mma16(float acc[4],
                                      unsigned a0, unsigned a1,
                                      unsigned a2, unsigned a3,
                                      unsigned b0, unsigned b1)
{
    asm volatile(
        "mma.sync.aligned.m16n8k16.row.col.f32.f16.f16.f32 "
        "{%0,%1,%2,%3}, {%4,%5,%6,%7}, {%8,%9}, {%0,%1,%2,%3};"
        : "+f"(acc[0]), "+f"(acc[1]), "+f"(acc[2]), "+f"(acc[3])
        : "r"(a0), "r"(a1), "r"(a2), "r"(a3), "r"(b0), "r"(b1));
}

__device__ __forceinline__ unsigned pack_h2(float lo, float hi) {
    __half2 h = __floats2half2_rn(lo, hi);
    return *reinterpret_cast<unsigned*>(&h);
}

__device__ __forceinline__ unsigned hmul2u(unsigned w, __half2 qh) {
    __half2 a = *reinterpret_cast<__half2*>(&w);
    __half2 r = __hmul2(a, qh);
    return *reinterpret_cast<unsigned*>(&r);
}

// Within-chunk word for column c: pairs (c, c+4) adjacent for LDS.64 frags.
__device__ __forceinline__ int withinc(int c) {
    return ((c & 3) << 1) | ((c >> 2) & 1);
}
// Same idea for half2-pair index p (0..7 within a k16 chunk).
__device__ __forceinline__ int pslot(int p) {
    return ((p & 3) << 1) | (p >> 2);
}

// ---------------------------------------------------------------------------
// Kernel 0a: weight transpose for h-projections (+scale fold for Wk/Wk2).
// ---------------------------------------------------------------------------
__global__ __launch_bounds__(256) void transpose_kernel(
    const float* __restrict__ Wq, const float* __restrict__ Wk,
    const float* __restrict__ Wv, const float* __restrict__ Wq2,
    const float* __restrict__ Wk2)
{
    __shared__ float t[32][33];
    int m = blockIdx.z;
    int n0 = blockIdx.x * 32, c0 = blockIdx.y * 32;
    const float* src;
    float* dst;
    float scale = 1.0f;
    switch (m) {
        case 0: src = Wq;  dst = g_WTh;                break;
        case 1: src = Wk;  dst = g_WTh + 512 * 128;    scale = 0.125f; break;
        case 2: src = Wv;  dst = g_WTh + 2 * 512 * 128; break;
        case 3: src = Wq2; dst = g_WTh + 3 * 512 * 128; break;
        default: src = Wk2; dst = g_WTh + 4 * 512 * 128; scale = 0.125f; break;
    }
    int tx = threadIdx.x & 31, ty = threadIdx.x >> 5;
#pragma unroll
    for (int i = 0; i < 4; ++i)
        t[ty + i * 8][tx] = src[(c0 + ty + i * 8) * 512 + n0 + tx] * scale;
    __syncthreads();
#pragma unroll
    for (int i = 0; i < 4; ++i)
        dst[(long)(n0 + ty + i * 8) * 128 + c0 + tx] = t[tx][ty + i * 8];
}

// ---------------------------------------------------------------------------
// Kernel 0b: pack We/We2 into half2 MMA B-fragment order (g_WTeh).
// One thread per (g, k, q, kc) entry; 16384 threads total.
// ---------------------------------------------------------------------------
__global__ __launch_bounds__(256) void wte_pack_kernel(
    const float* __restrict__ We, const float* __restrict__ We2)
{
    int idx = blockIdx.x * 256 + threadIdx.x;   // ((g*512+k)*4+q)*4+kc
    int kc = idx & 3;
    int q = (idx >> 2) & 3;
    int k = (idx >> 4) & 511;
    int g = idx >> 13;
    const float* W = g ? We2 : We;
    int c0 = kc * 16 + 2 * q;
    float w0 = W[c0 * 512 + k];
    float w1 = W[(c0 + 1) * 512 + k];
    float w2 = W[(c0 + 8) * 512 + k];
    float w3 = W[(c0 + 9) * 512 + k];
    unsigned* dst = g_WTeh + (((g << 9) | k) * 4 + q) * 8 + kc * 2;
    dst[0] = pack_h2(w0, w1);
    dst[1] = pack_h2(w2, w3);
}

// ---------------------------------------------------------------------------
// Kernel 1: projections via SPLIT tf32 MMA (3-term: hi*hi + lo*hi + hi*lo
// with lo = tf32(x - tf32(x))) -> ~fp32 accuracy on Q/K/V.
// ---------------------------------------------------------------------------
__global__ __launch_bounds__(256) void proj_kernel(const float* __restrict__ h)
{
    extern __shared__ float sm[];
    float* Ah = sm;            // [64 rows][64 words] xor-swizzled
    float* Al = Ah + 4096;
    float* Bh = Al + 4096;
    float* Bl = Bh + 4096;     // 64 KB total
    int tid = threadIdx.x;
    int lane = tid & 31, warp = tid >> 5;
    int q = lane & 3, r = lane >> 2;
    int col0 = blockIdx.x * 64, row0 = blockIdx.y * 64;
    int z = blockIdx.z;
    float* dst;
    switch (z) {
        case 0: dst = g_Qh; break;
        case 1: dst = g_Kh; break;
        case 2: dst = g_Vh; break;
        case 3: dst = g_Q2; break;
        default: dst = g_K2; break;
    }
    const float* WT = g_WTh + (long)z * 512 * 128;

    int mt = warp >> 1;
    int nts = (warp & 1) * 4;
    float acc[4][4];
#pragma unroll
    for (int t = 0; t < 4; ++t)
#pragma unroll
        for (int m = 0; m < 4; ++m) acc[t][m] = 0.0f;

    for (int ck = 0; ck < 2; ++ck) {
        __syncthreads();
        for (int f = tid; f < 4096; f += 256) {
            int rr = f >> 6, c = f & 63;
            int off = rr * 64 + ((((c >> 3) ^ (rr & 7)) << 3) | withinc(c));
            float av = h[(row0 + rr) * 128 + ck * 64 + c];
            float ah = f2tf(av);
            Ah[off] = ah; Al[off] = f2tf(av - ah);
            float bv = WT[(long)(col0 + rr) * 128 + ck * 64 + c];
            float bh = f2tf(bv);
            Bh[off] = bh; Bl[off] = f2tf(bv - bh);
        }
        __syncthreads();

        for (int kc = 0; kc < 8; ++kc) {
            int pc = ((kc ^ r) << 3) + q * 2;
            int a0off = (mt * 16 + r) * 64 + pc;
            int a1off = (mt * 16 + 8 + r) * 64 + pc;
            uint2 Ah0 = *(const uint2*)&Ah[a0off];
            uint2 Ah1 = *(const uint2*)&Ah[a1off];
            uint2 Al0 = *(const uint2*)&Al[a0off];
            uint2 Al1 = *(const uint2*)&Al[a1off];
#pragma unroll
            for (int t = 0; t < 4; ++t) {
                int boff = ((nts + t) * 8 + r) * 64 + pc;
                uint2 Bhv = *(const uint2*)&Bh[boff];
                uint2 Blv = *(const uint2*)&Bl[boff];
                mma8(acc[t], Ah0.x, Ah1.x, Ah0.y, Ah1.y, Bhv.x, Bhv.y);
                mma8(acc[t], Al0.x, Al1.x, Al0.y, Al1.y, Bhv.x, Bhv.y);
                mma8(acc[t], Ah0.x, Ah1.x, Ah0.y, Ah1.y, Blv.x, Blv.y);
            }
        }
    }

#pragma unroll
    for (int t = 0; t < 4; ++t) {
        long b0 = (long)(row0 + mt * 16 + r) * 512 + col0 + (nts + t) * 8 + q * 2;
        long b1 = b0 + 8L * 512;
        *(float2*)&dst[b0] = make_float2(acc[t][0], acc[t][1]);
        *(float2*)&dst[b1] = make_float2(acc[t][2], acc[t][3]);
    }
}

// ---------------------------------------------------------------------------
// Kernel 2: fp16 tensor-core scores (m16n8k16, fp32 accum).
// Block = (b,i), 512 threads = 16 warps = (head, k-half).
// B-fragments: 2 x LDG.128 from pre-packed g_WTeh + __hmul2 Q-fold per s.
// ---------------------------------------------------------------------------
__global__ __launch_bounds__(512) void score_kernel(
    const float* __restrict__ e, const unsigned* __restrict__ adjw)
{
    extern __shared__ float sm[];
    unsigned* e_u = (unsigned*)sm;    // [144 slots][32 half2-units] swizzled
    float* q1   = sm + 4608;          // [512]
    float* q2   = q1 + 512;           // [512]
    float* sc_s = q2 + 512;           // [2 khalf][8 head][128 j]
    int*   cnt  = (int*)(sc_s + 2048);
    unsigned char* jlA    = (unsigned char*)(cnt + 2);   // [128]
    unsigned char* jlB    = jlA + 128;                   // [128]
    unsigned char* slot_j = jlB + 128;                   // [144]

    int tid = threadIdx.x;
    int lane = tid & 31, warp = tid >> 5;
    int q = lane & 3, r = lane >> 2;
    int head = warp >> 1, half = warp & 1;
    int b = blockIdx.x >> 7, i = blockIdx.x & 127;
    long base_e = ((long)(b * 128 + i)) * 8192;

    if (tid < 2) cnt[tid] = 0;
    __syncthreads();
    if (tid < 128) {
        unsigned a = adjw[(b * 128 + i) * 128 + tid];
        int lst = (a != 0u) ? 0 : 1;
        int pos = atomicAdd(&cnt[lst], 1);
        (lst == 0 ? jlA : jlB)[pos] = (unsigned char)tid;
    }
    q1[tid] = g_Qh[(long)(b * 128 + i) * 512 + tid];
    q2[tid] = g_Q2[(long)(b * 128 + i) * 512 + tid];
    __syncthreads();

    int n1 = cnt[0], n2 = cnt[1];
    int n1p = n1 ? ((n1 + 15) & ~15) : 0;
    int n2p = n2 ? ((n2 + 15) & ~15) : 0;
    int T1 = n1p >> 4;
    int T = (n1p + n2p) >> 4;
    int nslot = T << 4;
    if (tid < n1p) {
        slot_j[tid] = jlA[tid < n1 ? tid : n1 - 1];
    } else if (tid - n1p < n2p) {
        int s2 = tid - n1p;
        slot_j[tid] = jlB[s2 < n2 ? s2 : n2 - 1];
    }
    __syncthreads();

    // Load e rows (sorted slot order) as half2, swizzled.
    for (int f = tid; f < nslot * 16; f += 512) {
        int slot = f >> 4, t4 = f & 15;
        int j = slot_j[slot];
        float4 v = *(const float4*)&e[base_e + j * 64 + t4 * 4];
        int chunk = t4 >> 2;                    // k16-chunk (0..3)
        int phys = (chunk ^ (slot & 3)) << 3;
        int pw0 = (2 * t4) & 7;                 // even pair in chunk
        unsigned* row = e_u + slot * 32 + phys;
        row[pslot(pw0)]     = pack_h2(v.x, v.y);
        row[pslot(pw0 + 1)] = pack_h2(v.z, v.w);
    }
    __syncthreads();

    int kbase = head * 64 + half * 32;
    for (int g = 0; g < 2; ++g) {
        int t0 = g ? T1 : 0;
        int t1 = g ? T : T1;
        if (t0 == t1) continue;
        const float* qs = g ? q2 : q1;
        const float* Ks = g ? g_K2 : g_Kh;

        // Build fp16 B fragments: 2 x LDG.128 + 4 x hmul2 per s.
        uint2 Bv[4][4];
#pragma unroll
        for (int s = 0; s < 4; ++s) {
            int krow = kbase + s * 8 + r;
            __half2 qh2 = __floats2half2_rn(qs[krow], qs[krow]);
            const uint4* wp = (const uint4*)(g_WTeh
                              + (((g << 9) | krow) * 4 + q) * 8);
            uint4 wa = wp[0], wb = wp[1];
            Bv[s][0].x = hmul2u(wa.x, qh2);
            Bv[s][0].y = hmul2u(wa.y, qh2);
            Bv[s][1].x = hmul2u(wa.z, qh2);
            Bv[s][1].y = hmul2u(wa.w, qh2);
            Bv[s][2].x = hmul2u(wb.x, qh2);
            Bv[s][2].y = hmul2u(wb.y, qh2);
            Bv[s][3].x = hmul2u(wb.z, qh2);
            Bv[s][3].y = hmul2u(wb.w, qh2);
        }

        for (int t = t0; t < t1; ++t) {
            int slot0 = t * 16 + r, slot1 = slot0 + 8;
            float acc[4][4];
#pragma unroll
            for (int s = 0; s < 4; ++s)
#pragma unroll
                for (int m = 0; m < 4; ++m) acc[s][m] = 0.0f;

#pragma unroll
            for (int kc = 0; kc < 4; ++kc) {
                int pc = ((kc ^ (r & 3)) << 3) + 2 * q;
                uint2 A0 = *(const uint2*)(e_u + slot0 * 32 + pc);
                uint2 A1 = *(const uint2*)(e_u + slot1 * 32 + pc);
#pragma unroll
                for (int s = 0; s < 4; ++s)
                    mma16(acc[s], A0.x, A1.x, A0.y, A1.y,
                          Bv[s][kc].x, Bv[s][kc].y);
            }

            // Epilogue: dot k-half with K, quad-reduce, store partial.
            int j0 = slot_j[slot0], j1 = slot_j[slot1];
            const float* K0 = Ks + (long)(b * 128 + j0) * 512 + kbase + q * 2;
            const float* K1 = Ks + (long)(b * 128 + j1) * 512 + kbase + q * 2;
            float p0 = 0.0f, p1 = 0.0f;
#pragma unroll
            for (int s = 0; s < 4; ++s) {
                float2 k0 = *(const float2*)(K0 + s * 8);
                float2 k1 = *(const float2*)(K1 + s * 8);
                p0 += acc[s][0] * k0.x + acc[s][1] * k0.y;
                p1 += acc[s][2] * k1.x + acc[s][3] * k1.y;
            }
            p0 += __shfl_xor_sync(0xffffffffu, p0, 1);
            p0 += __shfl_xor_sync(0xffffffffu, p0, 2);
            p1 += __shfl_xor_sync(0xffffffffu, p1, 1);
            p1 += __shfl_xor_sync(0xffffffffu, p1, 2);
            if (q == 0) {
                float* dstp = &sc_s[(half * 8 + head) * 128];
                dstp[j0] = p0;   // duplicate-padded slots store identical
                dstp[j1] = p1;   // values -> plain stores are safe
            }
        }
    }
    __syncthreads();

    for (int idx = tid; idx < 1024; idx += 512) {
        int hh = idx >> 7, j = idx & 127;
        float v = sc_s[hh * 128 + j] + sc_s[1024 + hh * 128 + j];
        g_sc[((long)((b * 8 + hh) * 128 + i)) * 128 + j] = v;
    }
}

// ---------------------------------------------------------------------------
// Kernel 3: epilogue, no max subtraction (uniform shift cancels in the
// normalization). Block = (b, h, i-tile of 16).
// ---------------------------------------------------------------------------
__global__ __launch_bounds__(256) void out_kernel(
    const float* __restrict__ krw, const float* __restrict__ mask,
    float* __restrict__ out)
{
    __shared__ float Vs[8192];       // [128 j][64 k]
    __shared__ float ms[128];
    int tid = threadIdx.x;
    int lane = tid & 31, warp = tid >> 5;
    int blk = blockIdx.x;
    int b = blk >> 6, h = (blk >> 3) & 7, it = blk & 7;

    for (int f = tid; f < 8192; f += 256) {
        int j = f >> 6, k = f & 63;
        Vs[f] = g_Vh[(long)(b * 128 + j) * 512 + h * 64 + k];
    }
    if (tid < 128) ms[tid] = mask[b * 128 + tid];
    __syncthreads();

#pragma unroll
    for (int rr = 0; rr < 2; ++rr) {
        int i = it * 16 + warp * 2 + rr;
        float mi = ms[i];
        float pm[4];
        float den = 0.0f;
#pragma unroll
        for (int m = 0; m < 4; ++m) {
            int j = m * 32 + lane;
            float s = g_sc[((long)((b * 8 + h) * 128 + i)) * 128 + j];
            float p = __expf(s) * ms[j] * krw[(long)b * 16384 + i * 128 + j];
            pm[m] = p;
            den += p;
        }
#pragma unroll
        for (int o = 16; o; o >>= 1) den += __shfl_xor_sync(0xffffffffu, den, o);
        den = fmaxf(den * mi, 1e-6f);

        float a0 = 0.0f, a1 = 0.0f;
#pragma unroll
        for (int m = 0; m < 4; ++m) {
#pragma unroll 8
            for (int jj = 0; jj < 32; ++jj) {
                float p = __shfl_sync(0xffffffffu, pm[m], jj);
                int j = m * 32 + jj;
                a0 += p * Vs[j * 64 + lane];
                a1 += p * Vs[j * 64 + lane + 32];
            }
        }
        float inv = mi / den;
        long ob = (long)(b * 128 + i) * 512 + h * 64;
        out[ob + lane] = a0 * inv;
        out[ob + lane + 32] = a1 * inv;
    }
}

// ---------------------------------------------------------------------------
extern "C" void kernel_launch(void* const* d_in, const int* in_sizes, int n_in,
                              void* d_out, int out_size)
{
    (void)in_sizes; (void)n_in; (void)out_size;
    const float*    h    = (const float*)d_in[0];
    const float*    e    = (const float*)d_in[1];
    const float*    krw  = (const float*)d_in[2];
    const float*    mask = (const float*)d_in[3];
    const unsigned* adjw = (const unsigned*)d_in[4];
    const float*    Wq   = (const float*)d_in[5];
    const float*    Wk   = (const float*)d_in[6];
    const float*    Wv   = (const float*)d_in[7];
    const float*    We   = (const float*)d_in[8];
    const float*    Wq2  = (const float*)d_in[9];
    const float*    Wk2  = (const float*)d_in[10];
    const float*    We2  = (const float*)d_in[11];
    float* out = (float*)d_out;

    cudaFuncSetAttribute(proj_kernel,
                         cudaFuncAttributeMaxDynamicSharedMemorySize, 65536);
    // score smem: 4608*4 (e half2) + 1024*4 (q) + 2048*4 (sc) + 8 + 400
    //           = 31128 -> 31232 B
    cudaFuncSetAttribute(score_kernel,
                         cudaFuncAttributeMaxDynamicSharedMemorySize, 31232);

    transpose_kernel<<<dim3(16, 4, 5), 256>>>(Wq, Wk, Wv, Wq2, Wk2);
    wte_pack_kernel<<<64, 256>>>(We, We2);
    proj_kernel<<<dim3(8, 16, 5), 256, 65536>>>(h);
    score_kernel<<<1024, 512, 31232>>>(e, adjw);
    out_kernel<<<512, 256>>>(krw, mask, out);
}